// round 13
// baseline (speedup 1.0000x reference)
#include <cuda_runtime.h>
#include <cuda_fp16.h>
#include <math.h>
#include <stdint.h>

#define C_DIM 768
#define T_DIM 1024
#define B_DIM 8
#define H_NUM 12
#define HD    64
#define M_TOT 8192
#define S_ELE 6291456   /* 8*1024*768 */
#define X_ELE 6291456
#define W_ELE 589824    /* 768*768 */

static __device__ __align__(16) __half g_x[X_ELE];
static __device__ __align__(16) __half g_w[4 * W_ELE];
static __device__ __align__(16) __half g_qp[S_ELE];
static __device__ __align__(16) __half g_kp[S_ELE];
static __device__ __align__(16) __half g_vp[S_ELE];
static __device__ __align__(16) __half g_yp[S_ELE];
static __device__ float g_inv[32];

__device__ __forceinline__ uint32_t smem_u32(const void* p) {
    uint32_t a;
    asm("{ .reg .u64 t; cvta.to.shared.u64 t, %1; cvt.u32.u64 %0, t; }"
        : "=r"(a) : "l"(p));
    return a;
}
__device__ __forceinline__ float ex2f(float x) {
    float r;
    asm("ex2.approx.ftz.f32 %0, %1;" : "=f"(r) : "f"(x));
    return r;
}
__device__ __forceinline__ uint32_t pack_h2(float lo, float hi) {
    uint32_t u;
    asm("cvt.rn.f16x2.f32 %0, %1, %2;" : "=r"(u) : "f"(hi), "f"(lo));
    return u;
}
__device__ __forceinline__ void cpa16(uint32_t dst, const void* src) {
    asm volatile("cp.async.cg.shared.global [%0], [%1], 16;"
                 :: "r"(dst), "l"(src) : "memory");
}
#define CP_COMMIT()  asm volatile("cp.async.commit_group;" ::: "memory")
#define CP_WAIT(n)   asm volatile("cp.async.wait_group %0;" :: "n"(n) : "memory")
__device__ __forceinline__ void ldmx4(uint32_t& r0, uint32_t& r1,
                                      uint32_t& r2, uint32_t& r3, uint32_t addr) {
    asm volatile("ldmatrix.sync.aligned.m8n8.x4.shared.b16 {%0,%1,%2,%3}, [%4];"
                 : "=r"(r0), "=r"(r1), "=r"(r2), "=r"(r3) : "r"(addr));
}
__device__ __forceinline__ void ldmx4t(uint32_t& r0, uint32_t& r1,
                                       uint32_t& r2, uint32_t& r3, uint32_t addr) {
    asm volatile("ldmatrix.sync.aligned.m8n8.x4.trans.shared.b16 {%0,%1,%2,%3}, [%4];"
                 : "=r"(r0), "=r"(r1), "=r"(r2), "=r"(r3) : "r"(addr));
}
__device__ __forceinline__ void mma_f16(float* c, const uint32_t* a,
                                        const uint32_t* b) {
    asm volatile(
        "mma.sync.aligned.m16n8k16.row.col.f32.f16.f16.f32 "
        "{%0,%1,%2,%3},{%4,%5,%6,%7},{%8,%9},{%0,%1,%2,%3};"
        : "+f"(c[0]), "+f"(c[1]), "+f"(c[2]), "+f"(c[3])
        : "r"(a[0]), "r"(a[1]), "r"(a[2]), "r"(a[3]), "r"(b[0]), "r"(b[1]));
}

__device__ __forceinline__ uint32_t aswz(int row, int seg) {
    return (uint32_t)(row * 128 + ((seg ^ (row & 7)) << 4));
}

// ===========================================================================
#define PREP_F4 ((X_ELE + 4 * W_ELE) / 4)
__global__ void prep_convert(const float* __restrict__ x,
                             const float* __restrict__ Wq,
                             const float* __restrict__ Wk,
                             const float* __restrict__ Wv,
                             const float* __restrict__ Wo)
{
    if (blockIdx.x == 0 && threadIdx.x < 32)
        g_inv[threadIdx.x] =
            (float)exp((double)threadIdx.x * -0.28782313662425575);

    size_t i4 = (size_t)blockIdx.x * 256 + threadIdx.x;
    if (i4 >= PREP_F4) return;
    size_t e = i4 * 4;
    if (e < X_ELE) {
        float4 v = *(const float4*)(x + e);
        *(uint2*)(g_x + e) = make_uint2(pack_h2(v.x, v.y), pack_h2(v.z, v.w));
    } else {
        size_t r = e - X_ELE;
        int w = (int)(r / W_ELE);
        size_t off = r - (size_t)w * W_ELE;
        const float* src = (w == 0) ? Wq : (w == 1) ? Wk : (w == 2) ? Wv : Wo;
        float4 v = *(const float4*)(src + off);
        *(uint2*)(g_w + (size_t)w * W_ELE + off) =
            make_uint2(pack_h2(v.x, v.y), pack_h2(v.z, v.w));
    }
}

// ===========================================================================
// fp16 GEMM + fused epilogues (unchanged from R12).
// ===========================================================================
#define NCHUNK 12
#define GPLANE 16384
#define GSTAGE (2 * GPLANE)
#define GSMEM  (3 * GSTAGE)
#define EPAD   132

__global__ __launch_bounds__(256, 2)
void split_gemm2(float* __restrict__ dst, int is_qkv)
{
    extern __shared__ __align__(1024) unsigned char sm8[];
    const uint32_t base = smem_u32(sm8);
    const int tid  = threadIdx.x;
    const int lane = tid & 31;
    const int wid  = tid >> 5;
    const int wm   = wid >> 2;
    const int wn   = wid & 3;
    const int n0 = blockIdx.x * 128;
    const int m0 = blockIdx.y * 128;

    int mode;
    const __half *As, *Bs;
    if (is_qkv) {
        mode = blockIdx.z;
        As = g_x;
        Bs = g_w + (size_t)mode * W_ELE;
    } else {
        mode = 3;
        As = g_yp;
        Bs = g_w + 3 * (size_t)W_ELE;
    }
    As += (size_t)m0 * C_DIM;
    Bs += (size_t)n0 * C_DIM;

    float acc[16][4];
#pragma unroll
    for (int i = 0; i < 16; i++)
#pragma unroll
        for (int j = 0; j < 4; j++) acc[i][j] = 0.0f;

    auto copy_chunk = [&](int c, uint32_t st) {
        const int k0 = c * 64;
#pragma unroll
        for (int i = 0; i < 4; i++) {
            int idx = tid + i * 256;
            int r = idx >> 3, sg = idx & 7;
            uint32_t so = aswz(r, sg);
            size_t go = (size_t)r * C_DIM + k0 + sg * 8;
            cpa16(st + so,          As + go);
            cpa16(st + GPLANE + so, Bs + go);
        }
    };

    copy_chunk(0, base);
    CP_COMMIT();
    copy_chunk(1, base + GSTAGE);
    CP_COMMIT();

    for (int c = 0; c < NCHUNK; c++) {
        const uint32_t st = base + (uint32_t)(c % 3) * GSTAGE;
        if (c + 2 < NCHUNK) {
            copy_chunk(c + 2, base + (uint32_t)((c + 2) % 3) * GSTAGE);
            CP_COMMIT();
            CP_WAIT(2);
        } else if (c + 1 < NCHUNK) {
            CP_WAIT(1);
        } else {
            CP_WAIT(0);
        }
        __syncthreads();

#pragma unroll
        for (int ks = 0; ks < 4; ks++) {
            const int sg = 2 * ks + (lane >> 4);
            uint32_t bf[4][2];
#pragma unroll
            for (int g = 0; g < 2; g++) {
                int row = wn * 32 + g * 16 + (lane & 15);
                uint32_t off = aswz(row, sg);
                uint32_t r0, r1, r2, r3;
                ldmx4(r0, r1, r2, r3, st + GPLANE + off);
                bf[2 * g][0] = r0; bf[2 * g + 1][0] = r1;
                bf[2 * g][1] = r2; bf[2 * g + 1][1] = r3;
            }
#pragma unroll
            for (int mt = 0; mt < 4; mt++) {
                int row = wm * 64 + mt * 16 + (lane & 15);
                uint32_t off = aswz(row, sg);
                uint32_t af[4];
                ldmx4(af[0], af[1], af[2], af[3], st + off);
#pragma unroll
                for (int nt = 0; nt < 4; nt++)
                    mma_f16(acc[mt * 4 + nt], af, bf[nt]);
            }
        }
        __syncthreads();
    }

    if (mode <= 1) {
        float* sp = (float*)sm8;
#pragma unroll
        for (int mt = 0; mt < 4; mt++) {
#pragma unroll
            for (int nt = 0; nt < 4; nt++) {
                const float* cc = acc[mt * 4 + nt];
                int col = wn * 32 + nt * 8 + ((lane & 3) << 1);
                int coff = col + ((col >> 6) << 1);
#pragma unroll
                for (int h2 = 0; h2 < 2; h2++) {
                    int row = wm * 64 + mt * 16 + (lane >> 2) + h2 * 8;
                    *(float2*)(sp + row * EPAD + coff) =
                        make_float2(cc[h2 * 2], cc[h2 * 2 + 1]);
                }
            }
        }
        __syncthreads();

        const int row = tid >> 1;
        const int hh  = tid & 1;
        const int m   = m0 + row;
        const int bb  = m >> 10, t = m & (T_DIM - 1);
        const int bh  = bb * H_NUM + (n0 >> 6) + hh;
        float* v = sp + row * EPAD + hh * 66;
        const float tf = (float)t;

        float ssum = 0.0f;
#pragma unroll
        for (int d = 0; d < 32; d++) {
            float sn, cs;
            sincosf(tf * g_inv[d], &sn, &cs);
            float a = v[d], b2 = v[d + 32];
            float o1 = a * cs - b2 * sn;
            float o2 = a * sn + b2 * cs;
            v[d] = o1; v[d + 32] = o2;
            ssum += o1 * o1 + o2 * o2;
        }
        const float rn = rsqrtf(ssum * (1.0f / 64.0f) + 1e-6f);
        const size_t doff = ((size_t)bh * T_DIM + t) * HD;

        if (mode == 0) {
            const float sc = rn * (0.125f * 1.4426950408889634f);
#pragma unroll
            for (int j = 0; j < 32; j++)
                *(uint32_t*)(g_qp + doff + 2 * j) =
                    pack_h2(v[2 * j] * sc, v[2 * j + 1] * sc);
        } else {
#pragma unroll
            for (int j = 0; j < 32; j++) {
                float a = v[2 * j] * rn, b2 = v[2 * j + 1] * rn;
                *(float2*)(dst + doff + 2 * j) = make_float2(a, b2);
                *(uint32_t*)(g_kp + doff + 2 * j) = pack_h2(a, b2);
            }
        }
        return;
    }

#pragma unroll
    for (int mt = 0; mt < 4; mt++) {
#pragma unroll
        for (int nt = 0; nt < 4; nt++) {
            const float* cc = acc[mt * 4 + nt];
            int r  = m0 + wm * 64 + mt * 16 + (lane >> 2);
            int cl = n0 + wn * 32 + nt * 8 + ((lane & 3) << 1);
#pragma unroll
            for (int h2 = 0; h2 < 2; h2++) {
                int rr = r + h2 * 8;
                float v0 = cc[h2 * 2], v1 = cc[h2 * 2 + 1];
                if (mode == 3) {
                    *(float2*)(dst + (size_t)rr * C_DIM + cl) = make_float2(v0, v1);
                } else {
                    const int bb = rr >> 10, t = rr & (T_DIM - 1);
                    const int h = cl >> 6, hd0 = cl & (HD - 1);
                    size_t o = (((size_t)(bb * H_NUM + h)) * T_DIM + t) * HD + hd0;
                    *(float2*)(dst + S_ELE + o) = make_float2(v0, v1);  // v_out
                    *(uint32_t*)(g_vp + o) = pack_h2(v0, v1);
                }
            }
        }
    }
}

// ===========================================================================
// fp16 flash attention: 64 q-rows x 128 k-cols, 128 threads (4 warps),
// 2 CTAs/SM for softmax/MMA overlap. Even diagonal tiles skip right half.
// smem: Q 8KB + 2 KV stages x 32KB = 72KB.
// ===========================================================================
#define AQS     8192
#define APLANE  16384
#define KVSTAGE (2 * APLANE)
#define ASMEM   (AQS + 2 * KVSTAGE)

__global__ __launch_bounds__(128, 2)
void attn_mma(void)
{
    extern __shared__ __align__(1024) unsigned char sm8[];
    const uint32_t base = smem_u32(sm8);
    const uint32_t Qs = base;
    const uint32_t kvbase = base + AQS;

    const int tid  = threadIdx.x;
    const int lane = tid & 31;
    const int wid  = tid >> 5;          // 0..3
    const int qt   = 15 - blockIdx.x;   // heavy first
    const int bh   = blockIdx.y;
    const int b    = bh / H_NUM;
    const int h    = bh - b * H_NUM;
    const int q0   = qt * 64;
    const int wr0  = wid * 16;
    const int dt   = qt >> 1;           // diagonal k-tile index
    const bool halfd = ((qt & 1) == 0); // right half of diag tile fully masked

    const __half* q_g = g_qp + (size_t)bh * T_DIM * HD;
    const __half* k_g = g_kp + (size_t)bh * T_DIM * HD;
    const __half* v_g = g_vp + (size_t)bh * T_DIM * HD;

    auto copy_kv = [&](int kt, uint32_t st) {
        const int k0 = kt * 128;
#pragma unroll
        for (int i = 0; i < 8; i++) {
            int idx = tid + i * 128;
            int r = idx >> 3, sg = idx & 7;
            uint32_t so = aswz(r, sg);
            size_t go = (size_t)(k0 + r) * HD + sg * 8;
            cpa16(st + so,          k_g + go);
            cpa16(st + APLANE + so, v_g + go);
        }
    };

#pragma unroll
    for (int i = 0; i < 4; i++) {
        int idx = tid + i * 128;
        int r = idx >> 3, sg = idx & 7;
        uint32_t so = aswz(r, sg);
        cpa16(Qs + so, q_g + (size_t)(q0 + r) * HD + sg * 8);
    }
    copy_kv(0, kvbase);
    CP_COMMIT();

    float o[8][4];
#pragma unroll
    for (int i = 0; i < 8; i++)
#pragma unroll
        for (int j = 0; j < 4; j++) o[i][j] = 0.0f;
    float m_a = -INFINITY, m_b = -INFINITY, l_a = 0.0f, l_b = 0.0f;

    for (int kt = 0; kt <= dt; kt++) {
        const uint32_t st = kvbase + (uint32_t)(kt & 1) * KVSTAGE;
        if (kt < dt) {
            copy_kv(kt + 1, kvbase + (uint32_t)((kt + 1) & 1) * KVSTAGE);
            CP_COMMIT();
            CP_WAIT(1);
        } else {
            CP_WAIT(0);
        }
        __syncthreads();
        const uint32_t sK = st, sV = st + APLANE;
        const bool diag = (kt == dt);
        const int np_max = (diag && halfd) ? 4 : 8;

        float s[16][4];
#pragma unroll
        for (int i = 0; i < 16; i++)
#pragma unroll
            for (int j = 0; j < 4; j++) s[i][j] = 0.0f;

#pragma unroll
        for (int ks = 0; ks < 4; ks++) {
            int arow = wr0 + (lane & 15);
            int aseg = ks * 2 + (lane >> 4);
            uint32_t aoff = aswz(arow, aseg);
            uint32_t af[4];
            ldmx4(af[0], af[1], af[2], af[3], Qs + aoff);
            for (int np = 0; np < np_max; np++) {
                int brow = np * 16 + (lane & 15);
                uint32_t boff = aswz(brow, aseg);
                uint32_t r0, r1, r2, r3;
                uint32_t bf[2][2];
                ldmx4(r0, r1, r2, r3, sK + boff);
                bf[0][0] = r0; bf[0][1] = r2; bf[1][0] = r1; bf[1][1] = r3;
#pragma unroll
                for (int g = 0; g < 2; g++)
                    mma_f16(s[np * 2 + g], af, bf[g]);
            }
        }

        if (diag) {
            const int ra = (lane >> 2), cb = ((lane & 3) << 1);
            const int k0 = kt * 128;
#pragma unroll
            for (int nt = 0; nt < 16; nt++) {
#pragma unroll
                for (int j = 0; j < 4; j++) {
                    int col = k0 + nt * 8 + cb + (j & 1);
                    int row = q0 + wr0 + ra + ((j >> 1) << 3);
                    if (col > row) s[nt][j] = -INFINITY;
                }
            }
        }

        float mx_a = -INFINITY, mx_b = -INFINITY;
#pragma unroll
        for (int nt = 0; nt < 16; nt++) {
            mx_a = fmaxf(mx_a, fmaxf(s[nt][0], s[nt][1]));
            mx_b = fmaxf(mx_b, fmaxf(s[nt][2], s[nt][3]));
        }
        mx_a = fmaxf(mx_a, __shfl_xor_sync(0xffffffffu, mx_a, 1));
        mx_a = fmaxf(mx_a, __shfl_xor_sync(0xffffffffu, mx_a, 2));
        mx_b = fmaxf(mx_b, __shfl_xor_sync(0xffffffffu, mx_b, 1));
        mx_b = fmaxf(mx_b, __shfl_xor_sync(0xffffffffu, mx_b, 2));

        const float mn_a = fmaxf(m_a, mx_a);
        const float mn_b = fmaxf(m_b, mx_b);
        const float ca = ex2f(m_a - mn_a);
        const float cbf = ex2f(m_b - mn_b);
        m_a = mn_a; m_b = mn_b;

        float sa = 0.0f, sb = 0.0f;
#pragma unroll
        for (int nt = 0; nt < 16; nt++) {
            s[nt][0] = ex2f(s[nt][0] - mn_a);
            s[nt][1] = ex2f(s[nt][1] - mn_a);
            s[nt][2] = ex2f(s[nt][2] - mn_b);
            s[nt][3] = ex2f(s[nt][3] - mn_b);
            sa += s[nt][0] + s[nt][1];
            sb += s[nt][2] + s[nt][3];
        }
        sa += __shfl_xor_sync(0xffffffffu, sa, 1);
        sa += __shfl_xor_sync(0xffffffffu, sa, 2);
        sb += __shfl_xor_sync(0xffffffffu, sb, 1);
        sb += __shfl_xor_sync(0xffffffffu, sb, 2);
        l_a = l_a * ca + sa;
        l_b = l_b * cbf + sb;
#pragma unroll
        for (int i = 0; i < 8; i++) {
            o[i][0] *= ca; o[i][1] *= ca; o[i][2] *= cbf; o[i][3] *= cbf;
        }

        const int kc_max = (diag && halfd) ? 4 : 8;
        for (int kc = 0; kc < kc_max; kc++) {
            uint32_t pa[4];
            pa[0] = pack_h2(s[2*kc][0],   s[2*kc][1]);
            pa[1] = pack_h2(s[2*kc][2],   s[2*kc][3]);
            pa[2] = pack_h2(s[2*kc+1][0], s[2*kc+1][1]);
            pa[3] = pack_h2(s[2*kc+1][2], s[2*kc+1][3]);

            int vrow = kc * 16 + (lane & 15);
#pragma unroll
            for (int s2 = 0; s2 < 4; s2++) {
                int vseg = s2 * 2 + (lane >> 4);
                uint32_t voff = aswz(vrow, vseg);
                uint32_t r0, r1, r2, r3;
                uint32_t vf[2][2];
                ldmx4t(r0, r1, r2, r3, sV + voff);
                vf[0][0] = r0; vf[0][1] = r1; vf[1][0] = r2; vf[1][1] = r3;
#pragma unroll
                for (int g = 0; g < 2; g++)
                    mma_f16(o[s2 * 2 + g], pa, vf[g]);
            }
        }
        __syncthreads();
    }

    const float ia = 1.0f / l_a, ib = 1.0f / l_b;
    const int ra = lane >> 2, cb = (lane & 3) << 1;
    const size_t ybase = ((size_t)(b * T_DIM + q0 + wr0 + ra)) * C_DIM + h * HD;
#pragma unroll
    for (int nt = 0; nt < 8; nt++) {
        int col = nt * 8 + cb;
        *(uint32_t*)(g_yp + ybase + col) = pack_h2(o[nt][0] * ia, o[nt][1] * ia);
        *(uint32_t*)(g_yp + ybase + 8 * C_DIM + col) =
            pack_h2(o[nt][2] * ib, o[nt][3] * ib);
    }
}

// ---------------------------------------------------------------------------
extern "C" void kernel_launch(void* const* d_in, const int* in_sizes, int n_in,
                              void* d_out, int out_size)
{
    const float* x  = (const float*)d_in[0];
    const float* Wq = (const float*)d_in[1];
    const float* Wk = (const float*)d_in[2];
    const float* Wv = (const float*)d_in[3];
    const float* Wo = (const float*)d_in[4];

    float* out   = (float*)d_out;
    float* y_out = out;
    float* k_out = out + S_ELE;   // v_out = k_out + S_ELE (contiguous)

    cudaFuncSetAttribute(split_gemm2, cudaFuncAttributeMaxDynamicSharedMemorySize,
                         GSMEM);
    cudaFuncSetAttribute(attn_mma, cudaFuncAttributeMaxDynamicSharedMemorySize,
                         ASMEM);

    prep_convert<<<(PREP_F4 + 255) / 256, 256>>>(x, Wq, Wk, Wv, Wo);

    split_gemm2<<<dim3(C_DIM / 128, M_TOT / 128, 3), 256, GSMEM>>>(k_out, 1);

    attn_mma<<<dim3(T_DIM / 64, B_DIM * H_NUM), 128, ASMEM>>>();

    split_gemm2<<<dim3(C_DIM / 128, M_TOT / 128, 1), 256, GSMEM>>>(y_out, 0);
}

// round 14
// speedup vs baseline: 1.7087x; 1.7087x over previous
#include <cuda_runtime.h>
#include <cuda_fp16.h>
#include <math.h>
#include <stdint.h>

#define C_DIM 768
#define T_DIM 1024
#define B_DIM 8
#define H_NUM 12
#define HD    64
#define M_TOT 8192
#define S_ELE 6291456   /* 8*1024*768 */
#define X_ELE 6291456
#define W_ELE 589824    /* 768*768 */

static __device__ __align__(16) __half g_x[X_ELE];
static __device__ __align__(16) __half g_w[4 * W_ELE];
static __device__ __align__(16) __half g_qp[S_ELE];
static __device__ __align__(16) __half g_kp[S_ELE];
static __device__ __align__(16) __half g_vp[S_ELE];
static __device__ __align__(16) __half g_yp[S_ELE];
static __device__ __align__(16) float2 g_tab[T_DIM * 32];  // (cos,sin) per (t,d)

__device__ __forceinline__ uint32_t smem_u32(const void* p) {
    uint32_t a;
    asm("{ .reg .u64 t; cvta.to.shared.u64 t, %1; cvt.u32.u64 %0, t; }"
        : "=r"(a) : "l"(p));
    return a;
}
__device__ __forceinline__ float ex2f(float x) {
    float r;
    asm("ex2.approx.ftz.f32 %0, %1;" : "=f"(r) : "f"(x));
    return r;
}
__device__ __forceinline__ uint32_t pack_h2(float lo, float hi) {
    uint32_t u;
    asm("cvt.rn.f16x2.f32 %0, %1, %2;" : "=r"(u) : "f"(hi), "f"(lo));
    return u;
}
__device__ __forceinline__ void cpa16(uint32_t dst, const void* src) {
    asm volatile("cp.async.cg.shared.global [%0], [%1], 16;"
                 :: "r"(dst), "l"(src) : "memory");
}
#define CP_COMMIT()  asm volatile("cp.async.commit_group;" ::: "memory")
#define CP_WAIT(n)   asm volatile("cp.async.wait_group %0;" :: "n"(n) : "memory")
__device__ __forceinline__ void ldmx4(uint32_t& r0, uint32_t& r1,
                                      uint32_t& r2, uint32_t& r3, uint32_t addr) {
    asm volatile("ldmatrix.sync.aligned.m8n8.x4.shared.b16 {%0,%1,%2,%3}, [%4];"
                 : "=r"(r0), "=r"(r1), "=r"(r2), "=r"(r3) : "r"(addr));
}
__device__ __forceinline__ void ldmx4t(uint32_t& r0, uint32_t& r1,
                                       uint32_t& r2, uint32_t& r3, uint32_t addr) {
    asm volatile("ldmatrix.sync.aligned.m8n8.x4.trans.shared.b16 {%0,%1,%2,%3}, [%4];"
                 : "=r"(r0), "=r"(r1), "=r"(r2), "=r"(r3) : "r"(addr));
}
__device__ __forceinline__ void mma_f16(float* c, const uint32_t* a,
                                        const uint32_t* b) {
    asm volatile(
        "mma.sync.aligned.m16n8k16.row.col.f32.f16.f16.f32 "
        "{%0,%1,%2,%3},{%4,%5,%6,%7},{%8,%9},{%0,%1,%2,%3};"
        : "+f"(c[0]), "+f"(c[1]), "+f"(c[2]), "+f"(c[3])
        : "r"(a[0]), "r"(a[1]), "r"(a[2]), "r"(a[3]), "r"(b[0]), "r"(b[1]));
}

__device__ __forceinline__ uint32_t aswz(int row, int seg) {
    return (uint32_t)(row * 128 + ((seg ^ (row & 7)) << 4));
}

// ===========================================================================
// prep: x/weights -> fp16 planes; rope cos/sin table (double precision)
// ===========================================================================
#define PREP_F4 ((X_ELE + 4 * W_ELE) / 4)
__global__ void prep_convert(const float* __restrict__ x,
                             const float* __restrict__ Wq,
                             const float* __restrict__ Wk,
                             const float* __restrict__ Wv,
                             const float* __restrict__ Wo)
{
    if (blockIdx.x < 128) {
        int idx = blockIdx.x * 256 + threadIdx.x;   // 0..32767
        int t = idx >> 5, d = idx & 31;
        double f = (double)t * exp((double)d * -0.28782313662425575);
        g_tab[idx] = make_float2((float)cos(f), (float)sin(f));
    }

    size_t i4 = (size_t)blockIdx.x * 256 + threadIdx.x;
    if (i4 >= PREP_F4) return;
    size_t e = i4 * 4;
    if (e < X_ELE) {
        float4 v = *(const float4*)(x + e);
        *(uint2*)(g_x + e) = make_uint2(pack_h2(v.x, v.y), pack_h2(v.z, v.w));
    } else {
        size_t r = e - X_ELE;
        int w = (int)(r / W_ELE);
        size_t off = r - (size_t)w * W_ELE;
        const float* src = (w == 0) ? Wq : (w == 1) ? Wk : (w == 2) ? Wv : Wo;
        float4 v = *(const float4*)(src + off);
        *(uint2*)(g_w + (size_t)w * W_ELE + off) =
            make_uint2(pack_h2(v.x, v.y), pack_h2(v.z, v.w));
    }
}

// ===========================================================================
// fp16 GEMM + fused epilogues (R12 structure; rope uses table).
// is_qkv=1: z=0 q (rope->g_qp), z=1 k (rope->dst fp32 + g_kp), z=2 v
//           (dst+S_ELE fp32 + g_vp).  is_qkv=0: y -> dst fp32 (BTC).
// ===========================================================================
#define NCHUNK 12
#define GPLANE 16384
#define GSTAGE (2 * GPLANE)
#define GSMEM  (3 * GSTAGE)
#define EPAD   132

__global__ __launch_bounds__(256, 2)
void split_gemm2(float* __restrict__ dst, int is_qkv)
{
    extern __shared__ __align__(1024) unsigned char sm8[];
    const uint32_t base = smem_u32(sm8);
    const int tid  = threadIdx.x;
    const int lane = tid & 31;
    const int wid  = tid >> 5;
    const int wm   = wid >> 2;
    const int wn   = wid & 3;
    const int n0 = blockIdx.x * 128;
    const int m0 = blockIdx.y * 128;

    int mode;
    const __half *As, *Bs;
    if (is_qkv) {
        mode = blockIdx.z;
        As = g_x;
        Bs = g_w + (size_t)mode * W_ELE;
    } else {
        mode = 3;
        As = g_yp;
        Bs = g_w + 3 * (size_t)W_ELE;
    }
    As += (size_t)m0 * C_DIM;
    Bs += (size_t)n0 * C_DIM;

    float acc[16][4];
#pragma unroll
    for (int i = 0; i < 16; i++)
#pragma unroll
        for (int j = 0; j < 4; j++) acc[i][j] = 0.0f;

    auto copy_chunk = [&](int c, uint32_t st) {
        const int k0 = c * 64;
#pragma unroll
        for (int i = 0; i < 4; i++) {
            int idx = tid + i * 256;
            int r = idx >> 3, sg = idx & 7;
            uint32_t so = aswz(r, sg);
            size_t go = (size_t)r * C_DIM + k0 + sg * 8;
            cpa16(st + so,          As + go);
            cpa16(st + GPLANE + so, Bs + go);
        }
    };

    copy_chunk(0, base);
    CP_COMMIT();
    copy_chunk(1, base + GSTAGE);
    CP_COMMIT();

    for (int c = 0; c < NCHUNK; c++) {
        const uint32_t st = base + (uint32_t)(c % 3) * GSTAGE;
        if (c + 2 < NCHUNK) {
            copy_chunk(c + 2, base + (uint32_t)((c + 2) % 3) * GSTAGE);
            CP_COMMIT();
            CP_WAIT(2);
        } else if (c + 1 < NCHUNK) {
            CP_WAIT(1);
        } else {
            CP_WAIT(0);
        }
        __syncthreads();

#pragma unroll
        for (int ks = 0; ks < 4; ks++) {
            const int sg = 2 * ks + (lane >> 4);
            uint32_t bf[4][2];
#pragma unroll
            for (int g = 0; g < 2; g++) {
                int row = wn * 32 + g * 16 + (lane & 15);
                uint32_t off = aswz(row, sg);
                uint32_t r0, r1, r2, r3;
                ldmx4(r0, r1, r2, r3, st + GPLANE + off);
                bf[2 * g][0] = r0; bf[2 * g + 1][0] = r1;
                bf[2 * g][1] = r2; bf[2 * g + 1][1] = r3;
            }
#pragma unroll
            for (int mt = 0; mt < 4; mt++) {
                int row = wm * 64 + mt * 16 + (lane & 15);
                uint32_t off = aswz(row, sg);
                uint32_t af[4];
                ldmx4(af[0], af[1], af[2], af[3], st + off);
#pragma unroll
                for (int nt = 0; nt < 4; nt++)
                    mma_f16(acc[mt * 4 + nt], af, bf[nt]);
            }
        }
        __syncthreads();
    }

    if (mode <= 1) {
        // ---- fused rope+norm epilogue (table-based) ----
        float* sp = (float*)sm8;
#pragma unroll
        for (int mt = 0; mt < 4; mt++) {
#pragma unroll
            for (int nt = 0; nt < 4; nt++) {
                const float* cc = acc[mt * 4 + nt];
                int col = wn * 32 + nt * 8 + ((lane & 3) << 1);
                int coff = col + ((col >> 6) << 1);
#pragma unroll
                for (int h2 = 0; h2 < 2; h2++) {
                    int row = wm * 64 + mt * 16 + (lane >> 2) + h2 * 8;
                    *(float2*)(sp + row * EPAD + coff) =
                        make_float2(cc[h2 * 2], cc[h2 * 2 + 1]);
                }
            }
        }
        __syncthreads();

        const int row = tid >> 1;
        const int hh  = tid & 1;
        const int m   = m0 + row;
        const int bb  = m >> 10, t = m & (T_DIM - 1);
        const int bh  = bb * H_NUM + (n0 >> 6) + hh;
        float* v = sp + row * EPAD + hh * 66;
        const float2* trow = g_tab + t * 32;

        float ssum = 0.0f;
#pragma unroll
        for (int d = 0; d < 32; d++) {
            float2 sc = trow[d];
            float a = v[d], b2 = v[d + 32];
            float o1 = a * sc.x - b2 * sc.y;
            float o2 = a * sc.y + b2 * sc.x;
            v[d] = o1; v[d + 32] = o2;
            ssum += o1 * o1 + o2 * o2;
        }
        const float rn = rsqrtf(ssum * (1.0f / 64.0f) + 1e-6f);
        const size_t doff = ((size_t)bh * T_DIM + t) * HD;

        if (mode == 0) {
            const float sc = rn * (0.125f * 1.4426950408889634f);
#pragma unroll
            for (int j = 0; j < 32; j++)
                *(uint32_t*)(g_qp + doff + 2 * j) =
                    pack_h2(v[2 * j] * sc, v[2 * j + 1] * sc);
        } else {
#pragma unroll
            for (int j = 0; j < 32; j++) {
                float a = v[2 * j] * rn, b2 = v[2 * j + 1] * rn;
                *(float2*)(dst + doff + 2 * j) = make_float2(a, b2);
                *(uint32_t*)(g_kp + doff + 2 * j) = pack_h2(a, b2);
            }
        }
        return;
    }

#pragma unroll
    for (int mt = 0; mt < 4; mt++) {
#pragma unroll
        for (int nt = 0; nt < 4; nt++) {
            const float* cc = acc[mt * 4 + nt];
            int r  = m0 + wm * 64 + mt * 16 + (lane >> 2);
            int cl = n0 + wn * 32 + nt * 8 + ((lane & 3) << 1);
#pragma unroll
            for (int h2 = 0; h2 < 2; h2++) {
                int rr = r + h2 * 8;
                float v0 = cc[h2 * 2], v1 = cc[h2 * 2 + 1];
                if (mode == 3) {
                    *(float2*)(dst + (size_t)rr * C_DIM + cl) = make_float2(v0, v1);
                } else {
                    const int bb = rr >> 10, t = rr & (T_DIM - 1);
                    const int h = cl >> 6, hd0 = cl & (HD - 1);
                    size_t o = (((size_t)(bb * H_NUM + h)) * T_DIM + t) * HD + hd0;
                    *(float2*)(dst + S_ELE + o) = make_float2(v0, v1);  // v_out
                    *(uint32_t*)(g_vp + o) = pack_h2(v0, v1);
                }
            }
        }
    }
}

// ===========================================================================
// fp16 flash attention (exact R12 version: 128 q-rows, 256 threads).
// ===========================================================================
#define APLANE  16384
#define KVSTAGE (2 * APLANE)
#define ASMEM   (APLANE + 2 * KVSTAGE)

__global__ __launch_bounds__(256, 1)
void attn_mma(void)
{
    extern __shared__ __align__(1024) unsigned char sm8[];
    const uint32_t base = smem_u32(sm8);
    const uint32_t Qs = base;
    const uint32_t kvbase = base + APLANE;

    const int tid  = threadIdx.x;
    const int lane = tid & 31;
    const int wid  = tid >> 5;
    const int qt   = 7 - blockIdx.x;
    const int bh   = blockIdx.y;
    const int b    = bh / H_NUM;
    const int h    = bh - b * H_NUM;
    const int q0   = qt * 128;
    const int wr0  = wid * 16;

    const __half* q_g = g_qp + (size_t)bh * T_DIM * HD;
    const __half* k_g = g_kp + (size_t)bh * T_DIM * HD;
    const __half* v_g = g_vp + (size_t)bh * T_DIM * HD;

    auto copy_kv = [&](int kt, uint32_t st) {
        const int k0 = kt * 128;
#pragma unroll
        for (int i = 0; i < 4; i++) {
            int idx = tid + i * 256;
            int r = idx >> 3, sg = idx & 7;
            uint32_t so = aswz(r, sg);
            size_t go = (size_t)(k0 + r) * HD + sg * 8;
            cpa16(st + so,          k_g + go);
            cpa16(st + APLANE + so, v_g + go);
        }
    };

#pragma unroll
    for (int i = 0; i < 4; i++) {
        int idx = tid + i * 256;
        int r = idx >> 3, sg = idx & 7;
        uint32_t so = aswz(r, sg);
        cpa16(Qs + so, q_g + (size_t)(q0 + r) * HD + sg * 8);
    }
    copy_kv(0, kvbase);
    CP_COMMIT();

    float o[8][4];
#pragma unroll
    for (int i = 0; i < 8; i++)
#pragma unroll
        for (int j = 0; j < 4; j++) o[i][j] = 0.0f;
    float m_a = -INFINITY, m_b = -INFINITY, l_a = 0.0f, l_b = 0.0f;

    for (int kt = 0; kt <= qt; kt++) {
        const uint32_t st = kvbase + (uint32_t)(kt & 1) * KVSTAGE;
        if (kt < qt) {
            copy_kv(kt + 1, kvbase + (uint32_t)((kt + 1) & 1) * KVSTAGE);
            CP_COMMIT();
            CP_WAIT(1);
        } else {
            CP_WAIT(0);
        }
        __syncthreads();
        const uint32_t sK = st, sV = st + APLANE;

        float s[16][4];
#pragma unroll
        for (int i = 0; i < 16; i++)
#pragma unroll
            for (int j = 0; j < 4; j++) s[i][j] = 0.0f;

#pragma unroll
        for (int ks = 0; ks < 4; ks++) {
            int arow = wr0 + (lane & 15);
            int aseg = ks * 2 + (lane >> 4);
            uint32_t aoff = aswz(arow, aseg);
            uint32_t af[4];
            ldmx4(af[0], af[1], af[2], af[3], Qs + aoff);
#pragma unroll
            for (int np = 0; np < 8; np++) {
                int brow = np * 16 + (lane & 15);
                uint32_t boff = aswz(brow, aseg);
                uint32_t r0, r1, r2, r3;
                uint32_t bf[2][2];
                ldmx4(r0, r1, r2, r3, sK + boff);
                bf[0][0] = r0; bf[0][1] = r2; bf[1][0] = r1; bf[1][1] = r3;
#pragma unroll
                for (int g = 0; g < 2; g++)
                    mma_f16(s[np * 2 + g], af, bf[g]);
            }
        }

        if (kt == qt) {
            const int ra = (lane >> 2), cb = ((lane & 3) << 1);
#pragma unroll
            for (int nt = 0; nt < 16; nt++) {
#pragma unroll
                for (int j = 0; j < 4; j++) {
                    int col = nt * 8 + cb + (j & 1);
                    int row = wr0 + ra + ((j >> 1) << 3);
                    if (col > row) s[nt][j] = -INFINITY;
                }
            }
        }

        float mx_a = -INFINITY, mx_b = -INFINITY;
#pragma unroll
        for (int nt = 0; nt < 16; nt++) {
            mx_a = fmaxf(mx_a, fmaxf(s[nt][0], s[nt][1]));
            mx_b = fmaxf(mx_b, fmaxf(s[nt][2], s[nt][3]));
        }
        mx_a = fmaxf(mx_a, __shfl_xor_sync(0xffffffffu, mx_a, 1));
        mx_a = fmaxf(mx_a, __shfl_xor_sync(0xffffffffu, mx_a, 2));
        mx_b = fmaxf(mx_b, __shfl_xor_sync(0xffffffffu, mx_b, 1));
        mx_b = fmaxf(mx_b, __shfl_xor_sync(0xffffffffu, mx_b, 2));

        const float mn_a = fmaxf(m_a, mx_a);
        const float mn_b = fmaxf(m_b, mx_b);
        const float ca = ex2f(m_a - mn_a);
        const float cbf = ex2f(m_b - mn_b);
        m_a = mn_a; m_b = mn_b;

        float sa = 0.0f, sb = 0.0f;
#pragma unroll
        for (int nt = 0; nt < 16; nt++) {
            s[nt][0] = ex2f(s[nt][0] - mn_a);
            s[nt][1] = ex2f(s[nt][1] - mn_a);
            s[nt][2] = ex2f(s[nt][2] - mn_b);
            s[nt][3] = ex2f(s[nt][3] - mn_b);
            sa += s[nt][0] + s[nt][1];
            sb += s[nt][2] + s[nt][3];
        }
        sa += __shfl_xor_sync(0xffffffffu, sa, 1);
        sa += __shfl_xor_sync(0xffffffffu, sa, 2);
        sb += __shfl_xor_sync(0xffffffffu, sb, 1);
        sb += __shfl_xor_sync(0xffffffffu, sb, 2);
        l_a = l_a * ca + sa;
        l_b = l_b * cbf + sb;
#pragma unroll
        for (int i = 0; i < 8; i++) {
            o[i][0] *= ca; o[i][1] *= ca; o[i][2] *= cbf; o[i][3] *= cbf;
        }

#pragma unroll
        for (int kc = 0; kc < 8; kc++) {
            uint32_t pa[4];
            pa[0] = pack_h2(s[2*kc][0],   s[2*kc][1]);
            pa[1] = pack_h2(s[2*kc][2],   s[2*kc][3]);
            pa[2] = pack_h2(s[2*kc+1][0], s[2*kc+1][1]);
            pa[3] = pack_h2(s[2*kc+1][2], s[2*kc+1][3]);

            int vrow = kc * 16 + (lane & 15);
#pragma unroll
            for (int s2 = 0; s2 < 4; s2++) {
                int vseg = s2 * 2 + (lane >> 4);
                uint32_t voff = aswz(vrow, vseg);
                uint32_t r0, r1, r2, r3;
                uint32_t vf[2][2];
                ldmx4t(r0, r1, r2, r3, sV + voff);
                vf[0][0] = r0; vf[0][1] = r1; vf[1][0] = r2; vf[1][1] = r3;
#pragma unroll
                for (int g = 0; g < 2; g++)
                    mma_f16(o[s2 * 2 + g], pa, vf[g]);
            }
        }
        __syncthreads();
    }

    const float ia = 1.0f / l_a, ib = 1.0f / l_b;
    const int ra = lane >> 2, cb = (lane & 3) << 1;
    const size_t ybase = ((size_t)(b * T_DIM + q0 + wr0 + ra)) * C_DIM + h * HD;
#pragma unroll
    for (int nt = 0; nt < 8; nt++) {
        int col = nt * 8 + cb;
        *(uint32_t*)(g_yp + ybase + col) = pack_h2(o[nt][0] * ia, o[nt][1] * ia);
        *(uint32_t*)(g_yp + ybase + 8 * C_DIM + col) =
            pack_h2(o[nt][2] * ib, o[nt][3] * ib);
    }
}

// ---------------------------------------------------------------------------
extern "C" void kernel_launch(void* const* d_in, const int* in_sizes, int n_in,
                              void* d_out, int out_size)
{
    const float* x  = (const float*)d_in[0];
    const float* Wq = (const float*)d_in[1];
    const float* Wk = (const float*)d_in[2];
    const float* Wv = (const float*)d_in[3];
    const float* Wo = (const float*)d_in[4];

    float* out   = (float*)d_out;
    float* y_out = out;
    float* k_out = out + S_ELE;   // v_out = k_out + S_ELE (contiguous)

    cudaFuncSetAttribute(split_gemm2, cudaFuncAttributeMaxDynamicSharedMemorySize,
                         GSMEM);
    cudaFuncSetAttribute(attn_mma, cudaFuncAttributeMaxDynamicSharedMemorySize,
                         ASMEM);

    prep_convert<<<(PREP_F4 + 255) / 256, 256>>>(x, Wq, Wk, Wv, Wo);

    split_gemm2<<<dim3(C_DIM / 128, M_TOT / 128, 3), 256, GSMEM>>>(k_out, 1);

    attn_mma<<<dim3(T_DIM / 128, B_DIM * H_NUM), 256, ASMEM>>>();

    split_gemm2<<<dim3(C_DIM / 128, M_TOT / 128, 1), 256, GSMEM>>>(y_out, 0);
}

// round 15
// speedup vs baseline: 1.7378x; 1.0170x over previous
#include <cuda_runtime.h>
#include <cuda_fp16.h>
#include <math.h>
#include <stdint.h>

#define C_DIM 768
#define T_DIM 1024
#define B_DIM 8
#define H_NUM 12
#define HD    64
#define M_TOT 8192
#define S_ELE 6291456   /* 8*1024*768 */
#define X_ELE 6291456
#define W_ELE 589824    /* 768*768 */

static __device__ __align__(16) __half g_x[X_ELE];
static __device__ __align__(16) __half g_w[4 * W_ELE];
static __device__ __align__(16) __half g_qp[S_ELE];
static __device__ __align__(16) __half g_kp[S_ELE];
static __device__ __align__(16) __half g_vp[S_ELE];
static __device__ __align__(16) __half g_yp[S_ELE];
static __device__ __align__(16) float2 g_tab[T_DIM * 32];  // (cos,sin) per (t,d)

__device__ __forceinline__ uint32_t smem_u32(const void* p) {
    uint32_t a;
    asm("{ .reg .u64 t; cvta.to.shared.u64 t, %1; cvt.u32.u64 %0, t; }"
        : "=r"(a) : "l"(p));
    return a;
}
__device__ __forceinline__ float ex2f(float x) {
    float r;
    asm("ex2.approx.ftz.f32 %0, %1;" : "=f"(r) : "f"(x));
    return r;
}
__device__ __forceinline__ uint32_t pack_h2(float lo, float hi) {
    uint32_t u;
    asm("cvt.rn.f16x2.f32 %0, %1, %2;" : "=r"(u) : "f"(hi), "f"(lo));
    return u;
}
__device__ __forceinline__ void cpa16(uint32_t dst, const void* src) {
    asm volatile("cp.async.cg.shared.global [%0], [%1], 16;"
                 :: "r"(dst), "l"(src) : "memory");
}
#define CP_COMMIT()  asm volatile("cp.async.commit_group;" ::: "memory")
#define CP_WAIT(n)   asm volatile("cp.async.wait_group %0;" :: "n"(n) : "memory")
__device__ __forceinline__ void ldmx4(uint32_t& r0, uint32_t& r1,
                                      uint32_t& r2, uint32_t& r3, uint32_t addr) {
    asm volatile("ldmatrix.sync.aligned.m8n8.x4.shared.b16 {%0,%1,%2,%3}, [%4];"
                 : "=r"(r0), "=r"(r1), "=r"(r2), "=r"(r3) : "r"(addr));
}
__device__ __forceinline__ void ldmx4t(uint32_t& r0, uint32_t& r1,
                                       uint32_t& r2, uint32_t& r3, uint32_t addr) {
    asm volatile("ldmatrix.sync.aligned.m8n8.x4.trans.shared.b16 {%0,%1,%2,%3}, [%4];"
                 : "=r"(r0), "=r"(r1), "=r"(r2), "=r"(r3) : "r"(addr));
}
__device__ __forceinline__ void mma_f16(float* c, const uint32_t* a,
                                        const uint32_t* b) {
    asm volatile(
        "mma.sync.aligned.m16n8k16.row.col.f32.f16.f16.f32 "
        "{%0,%1,%2,%3},{%4,%5,%6,%7},{%8,%9},{%0,%1,%2,%3};"
        : "+f"(c[0]), "+f"(c[1]), "+f"(c[2]), "+f"(c[3])
        : "r"(a[0]), "r"(a[1]), "r"(a[2]), "r"(a[3]), "r"(b[0]), "r"(b[1]));
}

__device__ __forceinline__ uint32_t aswz(int row, int seg) {
    return (uint32_t)(row * 128 + ((seg ^ (row & 7)) << 4));
}

// ===========================================================================
// prep: x/weights -> fp16 planes; rope cos/sin table (double precision)
// ===========================================================================
#define PREP_F4 ((X_ELE + 4 * W_ELE) / 4)
__global__ void prep_convert(const float* __restrict__ x,
                             const float* __restrict__ Wq,
                             const float* __restrict__ Wk,
                             const float* __restrict__ Wv,
                             const float* __restrict__ Wo)
{
    if (blockIdx.x < 128) {
        int idx = blockIdx.x * 256 + threadIdx.x;   // 0..32767
        int t = idx >> 5, d = idx & 31;
        double f = (double)t * exp((double)d * -0.28782313662425575);
        g_tab[idx] = make_float2((float)cos(f), (float)sin(f));
    }

    size_t i4 = (size_t)blockIdx.x * 256 + threadIdx.x;
    if (i4 >= PREP_F4) return;
    size_t e = i4 * 4;
    if (e < X_ELE) {
        float4 v = *(const float4*)(x + e);
        *(uint2*)(g_x + e) = make_uint2(pack_h2(v.x, v.y), pack_h2(v.z, v.w));
    } else {
        size_t r = e - X_ELE;
        int w = (int)(r / W_ELE);
        size_t off = r - (size_t)w * W_ELE;
        const float* src = (w == 0) ? Wq : (w == 1) ? Wk : (w == 2) ? Wv : Wo;
        float4 v = *(const float4*)(src + off);
        *(uint2*)(g_w + (size_t)w * W_ELE + off) =
            make_uint2(pack_h2(v.x, v.y), pack_h2(v.z, v.w));
    }
}

// ===========================================================================
// fp16 GEMM + fused epilogues (unchanged from R14).
// ===========================================================================
#define NCHUNK 12
#define GPLANE 16384
#define GSTAGE (2 * GPLANE)
#define GSMEM  (3 * GSTAGE)
#define EPAD   132

__global__ __launch_bounds__(256, 2)
void split_gemm2(float* __restrict__ dst, int is_qkv)
{
    extern __shared__ __align__(1024) unsigned char sm8[];
    const uint32_t base = smem_u32(sm8);
    const int tid  = threadIdx.x;
    const int lane = tid & 31;
    const int wid  = tid >> 5;
    const int wm   = wid >> 2;
    const int wn   = wid & 3;
    const int n0 = blockIdx.x * 128;
    const int m0 = blockIdx.y * 128;

    int mode;
    const __half *As, *Bs;
    if (is_qkv) {
        mode = blockIdx.z;
        As = g_x;
        Bs = g_w + (size_t)mode * W_ELE;
    } else {
        mode = 3;
        As = g_yp;
        Bs = g_w + 3 * (size_t)W_ELE;
    }
    As += (size_t)m0 * C_DIM;
    Bs += (size_t)n0 * C_DIM;

    float acc[16][4];
#pragma unroll
    for (int i = 0; i < 16; i++)
#pragma unroll
        for (int j = 0; j < 4; j++) acc[i][j] = 0.0f;

    auto copy_chunk = [&](int c, uint32_t st) {
        const int k0 = c * 64;
#pragma unroll
        for (int i = 0; i < 4; i++) {
            int idx = tid + i * 256;
            int r = idx >> 3, sg = idx & 7;
            uint32_t so = aswz(r, sg);
            size_t go = (size_t)r * C_DIM + k0 + sg * 8;
            cpa16(st + so,          As + go);
            cpa16(st + GPLANE + so, Bs + go);
        }
    };

    copy_chunk(0, base);
    CP_COMMIT();
    copy_chunk(1, base + GSTAGE);
    CP_COMMIT();

    for (int c = 0; c < NCHUNK; c++) {
        const uint32_t st = base + (uint32_t)(c % 3) * GSTAGE;
        if (c + 2 < NCHUNK) {
            copy_chunk(c + 2, base + (uint32_t)((c + 2) % 3) * GSTAGE);
            CP_COMMIT();
            CP_WAIT(2);
        } else if (c + 1 < NCHUNK) {
            CP_WAIT(1);
        } else {
            CP_WAIT(0);
        }
        __syncthreads();

#pragma unroll
        for (int ks = 0; ks < 4; ks++) {
            const int sg = 2 * ks + (lane >> 4);
            uint32_t bf[4][2];
#pragma unroll
            for (int g = 0; g < 2; g++) {
                int row = wn * 32 + g * 16 + (lane & 15);
                uint32_t off = aswz(row, sg);
                uint32_t r0, r1, r2, r3;
                ldmx4(r0, r1, r2, r3, st + GPLANE + off);
                bf[2 * g][0] = r0; bf[2 * g + 1][0] = r1;
                bf[2 * g][1] = r2; bf[2 * g + 1][1] = r3;
            }
#pragma unroll
            for (int mt = 0; mt < 4; mt++) {
                int row = wm * 64 + mt * 16 + (lane & 15);
                uint32_t off = aswz(row, sg);
                uint32_t af[4];
                ldmx4(af[0], af[1], af[2], af[3], st + off);
#pragma unroll
                for (int nt = 0; nt < 4; nt++)
                    mma_f16(acc[mt * 4 + nt], af, bf[nt]);
            }
        }
        __syncthreads();
    }

    if (mode <= 1) {
        // ---- fused rope+norm epilogue (table-based) ----
        float* sp = (float*)sm8;
#pragma unroll
        for (int mt = 0; mt < 4; mt++) {
#pragma unroll
            for (int nt = 0; nt < 4; nt++) {
                const float* cc = acc[mt * 4 + nt];
                int col = wn * 32 + nt * 8 + ((lane & 3) << 1);
                int coff = col + ((col >> 6) << 1);
#pragma unroll
                for (int h2 = 0; h2 < 2; h2++) {
                    int row = wm * 64 + mt * 16 + (lane >> 2) + h2 * 8;
                    *(float2*)(sp + row * EPAD + coff) =
                        make_float2(cc[h2 * 2], cc[h2 * 2 + 1]);
                }
            }
        }
        __syncthreads();

        const int row = tid >> 1;
        const int hh  = tid & 1;
        const int m   = m0 + row;
        const int bb  = m >> 10, t = m & (T_DIM - 1);
        const int bh  = bb * H_NUM + (n0 >> 6) + hh;
        float* v = sp + row * EPAD + hh * 66;
        const float2* trow = g_tab + t * 32;

        float ssum = 0.0f;
#pragma unroll
        for (int d = 0; d < 32; d++) {
            float2 sc = trow[d];
            float a = v[d], b2 = v[d + 32];
            float o1 = a * sc.x - b2 * sc.y;
            float o2 = a * sc.y + b2 * sc.x;
            v[d] = o1; v[d + 32] = o2;
            ssum += o1 * o1 + o2 * o2;
        }
        const float rn = rsqrtf(ssum * (1.0f / 64.0f) + 1e-6f);
        const size_t doff = ((size_t)bh * T_DIM + t) * HD;

        if (mode == 0) {
            const float sc = rn * (0.125f * 1.4426950408889634f);
#pragma unroll
            for (int j = 0; j < 32; j++)
                *(uint32_t*)(g_qp + doff + 2 * j) =
                    pack_h2(v[2 * j] * sc, v[2 * j + 1] * sc);
        } else {
#pragma unroll
            for (int j = 0; j < 32; j++) {
                float a = v[2 * j] * rn, b2 = v[2 * j + 1] * rn;
                *(float2*)(dst + doff + 2 * j) = make_float2(a, b2);
                *(uint32_t*)(g_kp + doff + 2 * j) = pack_h2(a, b2);
            }
        }
        return;
    }

#pragma unroll
    for (int mt = 0; mt < 4; mt++) {
#pragma unroll
        for (int nt = 0; nt < 4; nt++) {
            const float* cc = acc[mt * 4 + nt];
            int r  = m0 + wm * 64 + mt * 16 + (lane >> 2);
            int cl = n0 + wn * 32 + nt * 8 + ((lane & 3) << 1);
#pragma unroll
            for (int h2 = 0; h2 < 2; h2++) {
                int rr = r + h2 * 8;
                float v0 = cc[h2 * 2], v1 = cc[h2 * 2 + 1];
                if (mode == 3) {
                    *(float2*)(dst + (size_t)rr * C_DIM + cl) = make_float2(v0, v1);
                } else {
                    const int bb = rr >> 10, t = rr & (T_DIM - 1);
                    const int h = cl >> 6, hd0 = cl & (HD - 1);
                    size_t o = (((size_t)(bb * H_NUM + h)) * T_DIM + t) * HD + hd0;
                    *(float2*)(dst + S_ELE + o) = make_float2(v0, v1);  // v_out
                    *(uint32_t*)(g_vp + o) = pack_h2(v0, v1);
                }
            }
        }
    }
}

// ===========================================================================
// fp16 flash attention, NO-MAX softmax: after qk-RMSNorm, |logit*log2e| <=
// 8*log2e ~ 11.55 (Cauchy-Schwarz), so p = exp2(s) in [2^-12, 2^12] -- safe
// in fp16/fp32 with no max subtraction, no correction, no rescaling.
// ===========================================================================
#define APLANE  16384
#define KVSTAGE (2 * APLANE)
#define ASMEM   (APLANE + 2 * KVSTAGE)

__global__ __launch_bounds__(256, 1)
void attn_mma(void)
{
    extern __shared__ __align__(1024) unsigned char sm8[];
    const uint32_t base = smem_u32(sm8);
    const uint32_t Qs = base;
    const uint32_t kvbase = base + APLANE;

    const int tid  = threadIdx.x;
    const int lane = tid & 31;
    const int wid  = tid >> 5;
    const int qt   = 7 - blockIdx.x;
    const int bh   = blockIdx.y;
    const int b    = bh / H_NUM;
    const int h    = bh - b * H_NUM;
    const int q0   = qt * 128;
    const int wr0  = wid * 16;

    const __half* q_g = g_qp + (size_t)bh * T_DIM * HD;
    const __half* k_g = g_kp + (size_t)bh * T_DIM * HD;
    const __half* v_g = g_vp + (size_t)bh * T_DIM * HD;

    auto copy_kv = [&](int kt, uint32_t st) {
        const int k0 = kt * 128;
#pragma unroll
        for (int i = 0; i < 4; i++) {
            int idx = tid + i * 256;
            int r = idx >> 3, sg = idx & 7;
            uint32_t so = aswz(r, sg);
            size_t go = (size_t)(k0 + r) * HD + sg * 8;
            cpa16(st + so,          k_g + go);
            cpa16(st + APLANE + so, v_g + go);
        }
    };

#pragma unroll
    for (int i = 0; i < 4; i++) {
        int idx = tid + i * 256;
        int r = idx >> 3, sg = idx & 7;
        uint32_t so = aswz(r, sg);
        cpa16(Qs + so, q_g + (size_t)(q0 + r) * HD + sg * 8);
    }
    copy_kv(0, kvbase);
    CP_COMMIT();

    float o[8][4];
#pragma unroll
    for (int i = 0; i < 8; i++)
#pragma unroll
        for (int j = 0; j < 4; j++) o[i][j] = 0.0f;
    float l_a = 0.0f, l_b = 0.0f;

    for (int kt = 0; kt <= qt; kt++) {
        const uint32_t st = kvbase + (uint32_t)(kt & 1) * KVSTAGE;
        if (kt < qt) {
            copy_kv(kt + 1, kvbase + (uint32_t)((kt + 1) & 1) * KVSTAGE);
            CP_COMMIT();
            CP_WAIT(1);
        } else {
            CP_WAIT(0);
        }
        __syncthreads();
        const uint32_t sK = st, sV = st + APLANE;

        float s[16][4];
#pragma unroll
        for (int i = 0; i < 16; i++)
#pragma unroll
            for (int j = 0; j < 4; j++) s[i][j] = 0.0f;

#pragma unroll
        for (int ks = 0; ks < 4; ks++) {
            int arow = wr0 + (lane & 15);
            int aseg = ks * 2 + (lane >> 4);
            uint32_t aoff = aswz(arow, aseg);
            uint32_t af[4];
            ldmx4(af[0], af[1], af[2], af[3], Qs + aoff);
#pragma unroll
            for (int np = 0; np < 8; np++) {
                int brow = np * 16 + (lane & 15);
                uint32_t boff = aswz(brow, aseg);
                uint32_t r0, r1, r2, r3;
                uint32_t bf[2][2];
                ldmx4(r0, r1, r2, r3, sK + boff);
                bf[0][0] = r0; bf[0][1] = r2; bf[1][0] = r1; bf[1][1] = r3;
#pragma unroll
                for (int g = 0; g < 2; g++)
                    mma_f16(s[np * 2 + g], af, bf[g]);
            }
        }

        if (kt == qt) {
            const int ra = (lane >> 2), cb = ((lane & 3) << 1);
#pragma unroll
            for (int nt = 0; nt < 16; nt++) {
#pragma unroll
                for (int j = 0; j < 4; j++) {
                    int col = nt * 8 + cb + (j & 1);
                    int row = wr0 + ra + ((j >> 1) << 3);
                    if (col > row) s[nt][j] = -INFINITY;
                }
            }
        }

        // ---- no-max softmax: p = exp2(s), accumulate row sums ----
        float sa = 0.0f, sb = 0.0f;
#pragma unroll
        for (int nt = 0; nt < 16; nt++) {
            s[nt][0] = ex2f(s[nt][0]);
            s[nt][1] = ex2f(s[nt][1]);
            s[nt][2] = ex2f(s[nt][2]);
            s[nt][3] = ex2f(s[nt][3]);
            sa += s[nt][0] + s[nt][1];
            sb += s[nt][2] + s[nt][3];
        }
        sa += __shfl_xor_sync(0xffffffffu, sa, 1);
        sa += __shfl_xor_sync(0xffffffffu, sa, 2);
        sb += __shfl_xor_sync(0xffffffffu, sb, 1);
        sb += __shfl_xor_sync(0xffffffffu, sb, 2);
        l_a += sa;
        l_b += sb;

        // ---- O += P @ V ----
#pragma unroll
        for (int kc = 0; kc < 8; kc++) {
            uint32_t pa[4];
            pa[0] = pack_h2(s[2*kc][0],   s[2*kc][1]);
            pa[1] = pack_h2(s[2*kc][2],   s[2*kc][3]);
            pa[2] = pack_h2(s[2*kc+1][0], s[2*kc+1][1]);
            pa[3] = pack_h2(s[2*kc+1][2], s[2*kc+1][3]);

            int vrow = kc * 16 + (lane & 15);
#pragma unroll
            for (int s2 = 0; s2 < 4; s2++) {
                int vseg = s2 * 2 + (lane >> 4);
                uint32_t voff = aswz(vrow, vseg);
                uint32_t r0, r1, r2, r3;
                uint32_t vf[2][2];
                ldmx4t(r0, r1, r2, r3, sV + voff);
                vf[0][0] = r0; vf[0][1] = r1; vf[1][0] = r2; vf[1][1] = r3;
#pragma unroll
                for (int g = 0; g < 2; g++)
                    mma_f16(o[s2 * 2 + g], pa, vf[g]);
            }
        }
        __syncthreads();
    }

    const float ia = 1.0f / l_a, ib = 1.0f / l_b;
    const int ra = lane >> 2, cb = (lane & 3) << 1;
    const size_t ybase = ((size_t)(b * T_DIM + q0 + wr0 + ra)) * C_DIM + h * HD;
#pragma unroll
    for (int nt = 0; nt < 8; nt++) {
        int col = nt * 8 + cb;
        *(uint32_t*)(g_yp + ybase + col) = pack_h2(o[nt][0] * ia, o[nt][1] * ia);
        *(uint32_t*)(g_yp + ybase + 8 * C_DIM + col) =
            pack_h2(o[nt][2] * ib, o[nt][3] * ib);
    }
}

// ---------------------------------------------------------------------------
extern "C" void kernel_launch(void* const* d_in, const int* in_sizes, int n_in,
                              void* d_out, int out_size)
{
    const float* x  = (const float*)d_in[0];
    const float* Wq = (const float*)d_in[1];
    const float* Wk = (const float*)d_in[2];
    const float* Wv = (const float*)d_in[3];
    const float* Wo = (const float*)d_in[4];

    float* out   = (float*)d_out;
    float* y_out = out;
    float* k_out = out + S_ELE;   // v_out = k_out + S_ELE (contiguous)

    cudaFuncSetAttribute(split_gemm2, cudaFuncAttributeMaxDynamicSharedMemorySize,
                         GSMEM);
    cudaFuncSetAttribute(attn_mma, cudaFuncAttributeMaxDynamicSharedMemorySize,
                         ASMEM);

    prep_convert<<<(PREP_F4 + 255) / 256, 256>>>(x, Wq, Wk, Wv, Wo);

    split_gemm2<<<dim3(C_DIM / 128, M_TOT / 128, 3), 256, GSMEM>>>(k_out, 1);

    attn_mma<<<dim3(T_DIM / 128, B_DIM * H_NUM), 256, ASMEM>>>();

    split_gemm2<<<dim3(C_DIM / 128, M_TOT / 128, 1), 256, GSMEM>>>(y_out, 0);
}

// round 16
// speedup vs baseline: 1.7398x; 1.0012x over previous
#include <cuda_runtime.h>
#include <cuda_fp16.h>
#include <math.h>
#include <stdint.h>

#define C_DIM 768
#define T_DIM 1024
#define B_DIM 8
#define H_NUM 12
#define HD    64
#define M_TOT 8192
#define S_ELE 6291456   /* 8*1024*768 */
#define X_ELE 6291456
#define W_ELE 589824    /* 768*768 */

static __device__ __align__(16) __half g_x[X_ELE];
static __device__ __align__(16) __half g_w[4 * W_ELE];
static __device__ __align__(16) __half g_qp[S_ELE];
static __device__ __align__(16) __half g_kp[S_ELE];
static __device__ __align__(16) __half g_vp[S_ELE];
static __device__ __align__(16) __half g_yp[S_ELE];
static __device__ __align__(16) float2 g_tab[T_DIM * 32];  // (cos,sin) per (t,d)

__device__ __forceinline__ uint32_t smem_u32(const void* p) {
    uint32_t a;
    asm("{ .reg .u64 t; cvta.to.shared.u64 t, %1; cvt.u32.u64 %0, t; }"
        : "=r"(a) : "l"(p));
    return a;
}
__device__ __forceinline__ float ex2f(float x) {
    float r;
    asm("ex2.approx.ftz.f32 %0, %1;" : "=f"(r) : "f"(x));
    return r;
}
__device__ __forceinline__ uint32_t pack_h2(float lo, float hi) {
    uint32_t u;
    asm("cvt.rn.f16x2.f32 %0, %1, %2;" : "=r"(u) : "f"(hi), "f"(lo));
    return u;
}
__device__ __forceinline__ void cpa16(uint32_t dst, const void* src) {
    asm volatile("cp.async.cg.shared.global [%0], [%1], 16;"
                 :: "r"(dst), "l"(src) : "memory");
}
#define CP_COMMIT()  asm volatile("cp.async.commit_group;" ::: "memory")
#define CP_WAIT(n)   asm volatile("cp.async.wait_group %0;" :: "n"(n) : "memory")
__device__ __forceinline__ void ldmx4(uint32_t& r0, uint32_t& r1,
                                      uint32_t& r2, uint32_t& r3, uint32_t addr) {
    asm volatile("ldmatrix.sync.aligned.m8n8.x4.shared.b16 {%0,%1,%2,%3}, [%4];"
                 : "=r"(r0), "=r"(r1), "=r"(r2), "=r"(r3) : "r"(addr));
}
__device__ __forceinline__ void ldmx4t(uint32_t& r0, uint32_t& r1,
                                       uint32_t& r2, uint32_t& r3, uint32_t addr) {
    asm volatile("ldmatrix.sync.aligned.m8n8.x4.trans.shared.b16 {%0,%1,%2,%3}, [%4];"
                 : "=r"(r0), "=r"(r1), "=r"(r2), "=r"(r3) : "r"(addr));
}
__device__ __forceinline__ void mma_f16(float* c, const uint32_t* a,
                                        const uint32_t* b) {
    asm volatile(
        "mma.sync.aligned.m16n8k16.row.col.f32.f16.f16.f32 "
        "{%0,%1,%2,%3},{%4,%5,%6,%7},{%8,%9},{%0,%1,%2,%3};"
        : "+f"(c[0]), "+f"(c[1]), "+f"(c[2]), "+f"(c[3])
        : "r"(a[0]), "r"(a[1]), "r"(a[2]), "r"(a[3]), "r"(b[0]), "r"(b[1]));
}

__device__ __forceinline__ uint32_t aswz(int row, int seg) {
    return (uint32_t)(row * 128 + ((seg ^ (row & 7)) << 4));
}

// ===========================================================================
// prep: x/weights -> fp16 planes; rope cos/sin table (double precision)
// ===========================================================================
#define PREP_F4 ((X_ELE + 4 * W_ELE) / 4)
__global__ void prep_convert(const float* __restrict__ x,
                             const float* __restrict__ Wq,
                             const float* __restrict__ Wk,
                             const float* __restrict__ Wv,
                             const float* __restrict__ Wo)
{
    if (blockIdx.x < 128) {
        int idx = blockIdx.x * 256 + threadIdx.x;   // 0..32767
        int t = idx >> 5, d = idx & 31;
        double f = (double)t * exp((double)d * -0.28782313662425575);
        g_tab[idx] = make_float2((float)cos(f), (float)sin(f));
    }

    size_t i4 = (size_t)blockIdx.x * 256 + threadIdx.x;
    if (i4 >= PREP_F4) return;
    size_t e = i4 * 4;
    if (e < X_ELE) {
        float4 v = *(const float4*)(x + e);
        *(uint2*)(g_x + e) = make_uint2(pack_h2(v.x, v.y), pack_h2(v.z, v.w));
    } else {
        size_t r = e - X_ELE;
        int w = (int)(r / W_ELE);
        size_t off = r - (size_t)w * W_ELE;
        const float* src = (w == 0) ? Wq : (w == 1) ? Wk : (w == 2) ? Wv : Wo;
        float4 v = *(const float4*)(src + off);
        *(uint2*)(g_w + (size_t)w * W_ELE + off) =
            make_uint2(pack_h2(v.x, v.y), pack_h2(v.z, v.w));
    }
}

// ===========================================================================
// fp16 GEMM + fused epilogues (unchanged from R15).
// ===========================================================================
#define NCHUNK 12
#define GPLANE 16384
#define GSTAGE (2 * GPLANE)
#define GSMEM  (3 * GSTAGE)
#define EPAD   132

__global__ __launch_bounds__(256, 2)
void split_gemm2(float* __restrict__ dst, int is_qkv)
{
    extern __shared__ __align__(1024) unsigned char sm8[];
    const uint32_t base = smem_u32(sm8);
    const int tid  = threadIdx.x;
    const int lane = tid & 31;
    const int wid  = tid >> 5;
    const int wm   = wid >> 2;
    const int wn   = wid & 3;
    const int n0 = blockIdx.x * 128;
    const int m0 = blockIdx.y * 128;

    int mode;
    const __half *As, *Bs;
    if (is_qkv) {
        mode = blockIdx.z;
        As = g_x;
        Bs = g_w + (size_t)mode * W_ELE;
    } else {
        mode = 3;
        As = g_yp;
        Bs = g_w + 3 * (size_t)W_ELE;
    }
    As += (size_t)m0 * C_DIM;
    Bs += (size_t)n0 * C_DIM;

    float acc[16][4];
#pragma unroll
    for (int i = 0; i < 16; i++)
#pragma unroll
        for (int j = 0; j < 4; j++) acc[i][j] = 0.0f;

    auto copy_chunk = [&](int c, uint32_t st) {
        const int k0 = c * 64;
#pragma unroll
        for (int i = 0; i < 4; i++) {
            int idx = tid + i * 256;
            int r = idx >> 3, sg = idx & 7;
            uint32_t so = aswz(r, sg);
            size_t go = (size_t)r * C_DIM + k0 + sg * 8;
            cpa16(st + so,          As + go);
            cpa16(st + GPLANE + so, Bs + go);
        }
    };

    copy_chunk(0, base);
    CP_COMMIT();
    copy_chunk(1, base + GSTAGE);
    CP_COMMIT();

    for (int c = 0; c < NCHUNK; c++) {
        const uint32_t st = base + (uint32_t)(c % 3) * GSTAGE;
        if (c + 2 < NCHUNK) {
            copy_chunk(c + 2, base + (uint32_t)((c + 2) % 3) * GSTAGE);
            CP_COMMIT();
            CP_WAIT(2);
        } else if (c + 1 < NCHUNK) {
            CP_WAIT(1);
        } else {
            CP_WAIT(0);
        }
        __syncthreads();

#pragma unroll
        for (int ks = 0; ks < 4; ks++) {
            const int sg = 2 * ks + (lane >> 4);
            uint32_t bf[4][2];
#pragma unroll
            for (int g = 0; g < 2; g++) {
                int row = wn * 32 + g * 16 + (lane & 15);
                uint32_t off = aswz(row, sg);
                uint32_t r0, r1, r2, r3;
                ldmx4(r0, r1, r2, r3, st + GPLANE + off);
                bf[2 * g][0] = r0; bf[2 * g + 1][0] = r1;
                bf[2 * g][1] = r2; bf[2 * g + 1][1] = r3;
            }
#pragma unroll
            for (int mt = 0; mt < 4; mt++) {
                int row = wm * 64 + mt * 16 + (lane & 15);
                uint32_t off = aswz(row, sg);
                uint32_t af[4];
                ldmx4(af[0], af[1], af[2], af[3], st + off);
#pragma unroll
                for (int nt = 0; nt < 4; nt++)
                    mma_f16(acc[mt * 4 + nt], af, bf[nt]);
            }
        }
        __syncthreads();
    }

    if (mode <= 1) {
        // ---- fused rope+norm epilogue (table-based) ----
        float* sp = (float*)sm8;
#pragma unroll
        for (int mt = 0; mt < 4; mt++) {
#pragma unroll
            for (int nt = 0; nt < 4; nt++) {
                const float* cc = acc[mt * 4 + nt];
                int col = wn * 32 + nt * 8 + ((lane & 3) << 1);
                int coff = col + ((col >> 6) << 1);
#pragma unroll
                for (int h2 = 0; h2 < 2; h2++) {
                    int row = wm * 64 + mt * 16 + (lane >> 2) + h2 * 8;
                    *(float2*)(sp + row * EPAD + coff) =
                        make_float2(cc[h2 * 2], cc[h2 * 2 + 1]);
                }
            }
        }
        __syncthreads();

        const int row = tid >> 1;
        const int hh  = tid & 1;
        const int m   = m0 + row;
        const int bb  = m >> 10, t = m & (T_DIM - 1);
        const int bh  = bb * H_NUM + (n0 >> 6) + hh;
        float* v = sp + row * EPAD + hh * 66;
        const float2* trow = g_tab + t * 32;

        float ssum = 0.0f;
#pragma unroll
        for (int d = 0; d < 32; d++) {
            float2 sc = trow[d];
            float a = v[d], b2 = v[d + 32];
            float o1 = a * sc.x - b2 * sc.y;
            float o2 = a * sc.y + b2 * sc.x;
            v[d] = o1; v[d + 32] = o2;
            ssum += o1 * o1 + o2 * o2;
        }
        const float rn = rsqrtf(ssum * (1.0f / 64.0f) + 1e-6f);
        const size_t doff = ((size_t)bh * T_DIM + t) * HD;

        if (mode == 0) {
            const float sc = rn * (0.125f * 1.4426950408889634f);
#pragma unroll
            for (int j = 0; j < 32; j++)
                *(uint32_t*)(g_qp + doff + 2 * j) =
                    pack_h2(v[2 * j] * sc, v[2 * j + 1] * sc);
        } else {
#pragma unroll
            for (int j = 0; j < 32; j++) {
                float a = v[2 * j] * rn, b2 = v[2 * j + 1] * rn;
                *(float2*)(dst + doff + 2 * j) = make_float2(a, b2);
                *(uint32_t*)(g_kp + doff + 2 * j) = pack_h2(a, b2);
            }
        }
        return;
    }

#pragma unroll
    for (int mt = 0; mt < 4; mt++) {
#pragma unroll
        for (int nt = 0; nt < 4; nt++) {
            const float* cc = acc[mt * 4 + nt];
            int r  = m0 + wm * 64 + mt * 16 + (lane >> 2);
            int cl = n0 + wn * 32 + nt * 8 + ((lane & 3) << 1);
#pragma unroll
            for (int h2 = 0; h2 < 2; h2++) {
                int rr = r + h2 * 8;
                float v0 = cc[h2 * 2], v1 = cc[h2 * 2 + 1];
                if (mode == 3) {
                    *(float2*)(dst + (size_t)rr * C_DIM + cl) = make_float2(v0, v1);
                } else {
                    const int bb = rr >> 10, t = rr & (T_DIM - 1);
                    const int h = cl >> 6, hd0 = cl & (HD - 1);
                    size_t o = (((size_t)(bb * H_NUM + h)) * T_DIM + t) * HD + hd0;
                    *(float2*)(dst + S_ELE + o) = make_float2(v0, v1);  // v_out
                    *(uint32_t*)(g_vp + o) = pack_h2(v0, v1);
                }
            }
        }
    }
}

// ===========================================================================
// fp16 flash attention, no-max softmax, Q fragments hoisted to registers,
// 3-stage KV ring with a single __syncthreads per k-tile.
// smem: Q 16KB + 3 KV stages x 32KB = 112KB.
// ===========================================================================
#define APLANE  16384
#define KVSTAGE (2 * APLANE)
#define ASMEM   (APLANE + 3 * KVSTAGE)

__global__ __launch_bounds__(256, 1)
void attn_mma(void)
{
    extern __shared__ __align__(1024) unsigned char sm8[];
    const uint32_t base = smem_u32(sm8);
    const uint32_t Qs = base;
    const uint32_t kvbase = base + APLANE;

    const int tid  = threadIdx.x;
    const int lane = tid & 31;
    const int wid  = tid >> 5;
    const int qt   = 7 - blockIdx.x;
    const int bh   = blockIdx.y;
    const int b    = bh / H_NUM;
    const int h    = bh - b * H_NUM;
    const int q0   = qt * 128;
    const int wr0  = wid * 16;

    const __half* q_g = g_qp + (size_t)bh * T_DIM * HD;
    const __half* k_g = g_kp + (size_t)bh * T_DIM * HD;
    const __half* v_g = g_vp + (size_t)bh * T_DIM * HD;

    auto copy_kv = [&](int kt, uint32_t st) {
        const int k0 = kt * 128;
#pragma unroll
        for (int i = 0; i < 4; i++) {
            int idx = tid + i * 256;
            int r = idx >> 3, sg = idx & 7;
            uint32_t so = aswz(r, sg);
            size_t go = (size_t)(k0 + r) * HD + sg * 8;
            cpa16(st + so,          k_g + go);
            cpa16(st + APLANE + so, v_g + go);
        }
    };

#pragma unroll
    for (int i = 0; i < 4; i++) {
        int idx = tid + i * 256;
        int r = idx >> 3, sg = idx & 7;
        uint32_t so = aswz(r, sg);
        cpa16(Qs + so, q_g + (size_t)(q0 + r) * HD + sg * 8);
    }
    copy_kv(0, kvbase);
    CP_COMMIT();
    if (qt >= 1) { copy_kv(1, kvbase + KVSTAGE); }
    CP_COMMIT();     // commit (possibly empty) so group count is uniform

    float o[8][4];
#pragma unroll
    for (int i = 0; i < 8; i++)
#pragma unroll
        for (int j = 0; j < 4; j++) o[i][j] = 0.0f;
    float l_a = 0.0f, l_b = 0.0f;

    // Q fragments hoisted: af[ks][4]
    uint32_t aq[4][4];
    bool q_loaded = false;

    for (int kt = 0; kt <= qt; kt++) {
        const uint32_t st = kvbase + (uint32_t)(kt % 3) * KVSTAGE;
        if (kt + 1 < qt)      CP_WAIT(1);   // kt ready, kt+1 in flight
        else                  CP_WAIT(0);   // all issued copies done
        __syncthreads();                    // single barrier per iteration

        if (!q_loaded) {
            // Q copy completed with group 0 (first wait covers it)
#pragma unroll
            for (int ks = 0; ks < 4; ks++) {
                int arow = wr0 + (lane & 15);
                int aseg = ks * 2 + (lane >> 4);
                ldmx4(aq[ks][0], aq[ks][1], aq[ks][2], aq[ks][3],
                      Qs + aswz(arow, aseg));
            }
            q_loaded = true;
        }

        // prefetch kt+2 into the stage last read at kt-1 (safe: all warps
        // passed this barrier after reading it)
        if (kt + 2 <= qt) {
            copy_kv(kt + 2, kvbase + (uint32_t)((kt + 2) % 3) * KVSTAGE);
            CP_COMMIT();
        }

        const uint32_t sK = st, sV = st + APLANE;

        float s[16][4];
#pragma unroll
        for (int i = 0; i < 16; i++)
#pragma unroll
            for (int j = 0; j < 4; j++) s[i][j] = 0.0f;

#pragma unroll
        for (int ks = 0; ks < 4; ks++) {
            int aseg = ks * 2 + (lane >> 4);
#pragma unroll
            for (int np = 0; np < 8; np++) {
                int brow = np * 16 + (lane & 15);
                uint32_t boff = aswz(brow, aseg);
                uint32_t r0, r1, r2, r3;
                uint32_t bf[2][2];
                ldmx4(r0, r1, r2, r3, sK + boff);
                bf[0][0] = r0; bf[0][1] = r2; bf[1][0] = r1; bf[1][1] = r3;
#pragma unroll
                for (int g = 0; g < 2; g++)
                    mma_f16(s[np * 2 + g], aq[ks], bf[g]);
            }
        }

        if (kt == qt) {
            const int ra = (lane >> 2), cb = ((lane & 3) << 1);
#pragma unroll
            for (int nt = 0; nt < 16; nt++) {
#pragma unroll
                for (int j = 0; j < 4; j++) {
                    int col = nt * 8 + cb + (j & 1);
                    int row = wr0 + ra + ((j >> 1) << 3);
                    if (col > row) s[nt][j] = -INFINITY;
                }
            }
        }

        // ---- no-max softmax ----
        float sa = 0.0f, sb = 0.0f;
#pragma unroll
        for (int nt = 0; nt < 16; nt++) {
            s[nt][0] = ex2f(s[nt][0]);
            s[nt][1] = ex2f(s[nt][1]);
            s[nt][2] = ex2f(s[nt][2]);
            s[nt][3] = ex2f(s[nt][3]);
            sa += s[nt][0] + s[nt][1];
            sb += s[nt][2] + s[nt][3];
        }
        sa += __shfl_xor_sync(0xffffffffu, sa, 1);
        sa += __shfl_xor_sync(0xffffffffu, sa, 2);
        sb += __shfl_xor_sync(0xffffffffu, sb, 1);
        sb += __shfl_xor_sync(0xffffffffu, sb, 2);
        l_a += sa;
        l_b += sb;

        // ---- O += P @ V ----
#pragma unroll
        for (int kc = 0; kc < 8; kc++) {
            uint32_t pa[4];
            pa[0] = pack_h2(s[2*kc][0],   s[2*kc][1]);
            pa[1] = pack_h2(s[2*kc][2],   s[2*kc][3]);
            pa[2] = pack_h2(s[2*kc+1][0], s[2*kc+1][1]);
            pa[3] = pack_h2(s[2*kc+1][2], s[2*kc+1][3]);

            int vrow = kc * 16 + (lane & 15);
#pragma unroll
            for (int s2 = 0; s2 < 4; s2++) {
                int vseg = s2 * 2 + (lane >> 4);
                uint32_t voff = aswz(vrow, vseg);
                uint32_t r0, r1, r2, r3;
                uint32_t vf[2][2];
                ldmx4t(r0, r1, r2, r3, sV + voff);
                vf[0][0] = r0; vf[0][1] = r1; vf[1][0] = r2; vf[1][1] = r3;
#pragma unroll
                for (int g = 0; g < 2; g++)
                    mma_f16(o[s2 * 2 + g], pa, vf[g]);
            }
        }
    }

    const float ia = 1.0f / l_a, ib = 1.0f / l_b;
    const int ra = lane >> 2, cb = (lane & 3) << 1;
    const size_t ybase = ((size_t)(b * T_DIM + q0 + wr0 + ra)) * C_DIM + h * HD;
#pragma unroll
    for (int nt = 0; nt < 8; nt++) {
        int col = nt * 8 + cb;
        *(uint32_t*)(g_yp + ybase + col) = pack_h2(o[nt][0] * ia, o[nt][1] * ia);
        *(uint32_t*)(g_yp + ybase + 8 * C_DIM + col) =
            pack_h2(o[nt][2] * ib, o[nt][3] * ib);
    }
}

// ---------------------------------------------------------------------------
extern "C" void kernel_launch(void* const* d_in, const int* in_sizes, int n_in,
                              void* d_out, int out_size)
{
    const float* x  = (const float*)d_in[0];
    const float* Wq = (const float*)d_in[1];
    const float* Wk = (const float*)d_in[2];
    const float* Wv = (const float*)d_in[3];
    const float* Wo = (const float*)d_in[4];

    float* out   = (float*)d_out;
    float* y_out = out;
    float* k_out = out + S_ELE;   // v_out = k_out + S_ELE (contiguous)

    cudaFuncSetAttribute(split_gemm2, cudaFuncAttributeMaxDynamicSharedMemorySize,
                         GSMEM);
    cudaFuncSetAttribute(attn_mma, cudaFuncAttributeMaxDynamicSharedMemorySize,
                         ASMEM);

    prep_convert<<<(PREP_F4 + 255) / 256, 256>>>(x, Wq, Wk, Wv, Wo);

    split_gemm2<<<dim3(C_DIM / 128, M_TOT / 128, 3), 256, GSMEM>>>(k_out, 1);

    attn_mma<<<dim3(T_DIM / 128, B_DIM * H_NUM), 256, ASMEM>>>();

    split_gemm2<<<dim3(C_DIM / 128, M_TOT / 128, 1), 256, GSMEM>>>(y_out, 0);
}